// round 1
// baseline (speedup 1.0000x reference)
#include <cuda_runtime.h>
#include <math.h>

#define FF 32
#define BB 2048
#define KK 64
#define HH 64
#define NPAIR 496
#define NTHREADS 256
#define NWARP 8
#define SLOTS 512
#define SLOTS_PER_WARP 64

__global__ __launch_bounds__(NTHREADS) void afm_kernel(
    const int* __restrict__ x, const float* __restrict__ emb,
    const float* __restrict__ at_w, const float* __restrict__ at_b,
    const float* __restrict__ at_h, const float* __restrict__ pvec,
    const float* __restrict__ w0, const float* __restrict__ w1,
    float* __restrict__ out)
{
    __shared__ float sV[FF][KK];           // 8 KB   embedding rows for this b
    __shared__ float sW[KK][HH];           // 16 KB  at_w (k-major, h contiguous)
    __shared__ float sVV[NWARP][4][KK];    // 8 KB   4 staged pair-interaction vectors per warp
    __shared__ float sAth[HH];
    __shared__ float sAb[HH];
    __shared__ float sP[KK];
    __shared__ float sPooled[KK];
    __shared__ int   sX[FF];
    __shared__ unsigned char sPi[SLOTS], sPj[SLOTS];
    __shared__ float sFm1;

    const int b   = blockIdx.x;
    const int tid = threadIdx.x;
    const int w   = tid >> 5;
    const int L   = tid & 31;

    if (tid < FF) sX[tid] = x[tid * BB + b];
    if (tid < KK) {
        sPooled[tid] = 0.f;
        sAth[tid]    = at_h[tid];
        sAb[tid]     = at_b[tid];
        sP[tid]      = pvec[tid];
    }
    // pair-index table, padded to 512 slots (slots >= 496 are dummies)
    for (int pp = tid; pp < SLOTS; pp += NTHREADS) {
        if (pp < NPAIR) {
            int i = 0, rem = pp;
            while (rem >= FF - 1 - i) { rem -= FF - 1 - i; i++; }
            sPi[pp] = (unsigned char)i;
            sPj[pp] = (unsigned char)(i + 1 + rem);
        } else { sPi[pp] = 0; sPj[pp] = 0; }
    }
    for (int idx = tid; idx < KK * HH; idx += NTHREADS)
        (&sW[0][0])[idx] = at_w[idx];
    __syncthreads();

    // gather embedding rows (needs sX); consecutive tid -> consecutive k (coalesced)
    for (int idx = tid; idx < FF * KK; idx += NTHREADS) {
        int f = idx >> 6, k = idx & 63;
        sV[f][k] = emb[(long)sX[f] * KK + k];
    }
    __syncthreads();

    // first-order FM part (warp 0, overlapped with nothing critical)
    if (w == 0) {
        float v = w1[sX[L]];
        #pragma unroll
        for (int off = 16; off; off >>= 1) v += __shfl_xor_sync(0xffffffffu, v, off);
        if (L == 0) sFm1 = v + w0[0];
    }

    const float2 bv = *(const float2*)&sAb[2 * L];
    const float2 av = *(const float2*)&sAth[2 * L];
    float pooled0 = 0.f, pooled1 = 0.f;
    const int base = w * SLOTS_PER_WARP;

    for (int g0 = 0; g0 < SLOTS_PER_WARP; g0 += 4) {
        float vvA[4], vvB[4];
        #pragma unroll
        for (int pr = 0; pr < 4; pr++) {
            int p = base + g0 + pr;
            int i = sPi[p], j = sPj[p];
            float a0 = sV[i][L]      * sV[j][L];
            float a1 = sV[i][L + 32] * sV[j][L + 32];
            vvA[pr] = a0; vvB[pr] = a1;
            sVV[w][pr][L]      = a0;
            sVV[w][pr][L + 32] = a1;
        }
        __syncwarp();

        // hid = relu(VV @ W + b): lane owns columns h = 2L, 2L+1 for 4 pairs
        float2 acc[4] = {{0.f,0.f},{0.f,0.f},{0.f,0.f},{0.f,0.f}};
        #pragma unroll
        for (int k = 0; k < KK; k++) {
            float2 wv = *(const float2*)&sW[k][2 * L];
            #pragma unroll
            for (int pr = 0; pr < 4; pr++) {
                float vk = sVV[w][pr][k];               // broadcast
                acc[pr].x = fmaf(vk, wv.x, acc[pr].x);
                acc[pr].y = fmaf(vk, wv.y, acc[pr].y);
            }
        }

        float part[4];
        #pragma unroll
        for (int pr = 0; pr < 4; pr++) {
            float h0 = fmaxf(acc[pr].x + bv.x, 0.f);
            float h1 = fmaxf(acc[pr].y + bv.y, 0.f);
            part[pr] = h0 * av.x + h1 * av.y;
        }
        #pragma unroll
        for (int off = 16; off; off >>= 1) {
            #pragma unroll
            for (int pr = 0; pr < 4; pr++)
                part[pr] += __shfl_xor_sync(0xffffffffu, part[pr], off);
        }
        #pragma unroll
        for (int pr = 0; pr < 4; pr++) {
            int p   = base + g0 + pr;
            float s = (p < NPAIR) ? part[pr] : 0.f;     // kill padded slots
            pooled0 = fmaf(vvA[pr], s, pooled0);
            pooled1 = fmaf(vvB[pr], s, pooled1);
        }
        __syncwarp();   // protect sVV before next group's writes
    }

    atomicAdd(&sPooled[L],      pooled0);
    atomicAdd(&sPooled[L + 32], pooled1);
    __syncthreads();

    if (w == 0) {
        float d = sPooled[L] * sP[L] + sPooled[L + 32] * sP[L + 32];
        #pragma unroll
        for (int off = 16; off; off >>= 1) d += __shfl_xor_sync(0xffffffffu, d, off);
        if (L == 0) {
            float logit = d + sFm1;
            out[b] = 1.f / (1.f + expf(-logit));
        }
    }
}

extern "C" void kernel_launch(void* const* d_in, const int* in_sizes, int n_in,
                              void* d_out, int out_size) {
    (void)in_sizes; (void)n_in; (void)out_size;
    const int*   x    = (const int*)  d_in[0];
    const float* emb  = (const float*)d_in[1];
    const float* at_w = (const float*)d_in[2];
    const float* at_b = (const float*)d_in[3];
    const float* at_h = (const float*)d_in[4];
    const float* pvec = (const float*)d_in[5];
    const float* w0   = (const float*)d_in[6];
    const float* w1   = (const float*)d_in[7];
    float* out = (float*)d_out;

    afm_kernel<<<BB, NTHREADS>>>(x, emb, at_w, at_b, at_h, pvec, w0, w1, out);
}

// round 2
// speedup vs baseline: 1.0047x; 1.0047x over previous
#include <cuda_runtime.h>
#include <math.h>

#define FF 32
#define BB 2048
#define KK 64
#define HH 64
#define NPAIR 496
#define NTHREADS 256
#define NWARP 8
#define SLOTS 512
#define SLOTS_PER_WARP 64

__global__ __launch_bounds__(NTHREADS) void afm_kernel(
    const int* __restrict__ x, const float* __restrict__ emb,
    const float* __restrict__ at_w, const float* __restrict__ at_b,
    const float* __restrict__ at_h, const float* __restrict__ pvec,
    const float* __restrict__ w0, const float* __restrict__ w1,
    float* __restrict__ out)
{
    __shared__ float sV[FF][KK];            // 8 KB
    __shared__ float sW[KK][HH];            // 16 KB (k-major, h contiguous)
    __shared__ float sVVt[NWARP][KK][4];    // 8 KB  pair-minor: one float4 per k
    __shared__ float sAth[HH];
    __shared__ float sAb[HH];
    __shared__ float sP[KK];
    __shared__ float sPooled[KK];
    __shared__ int   sX[FF];
    __shared__ unsigned char sPi[SLOTS], sPj[SLOTS];
    __shared__ float sFm1;

    const int b   = blockIdx.x;
    const int tid = threadIdx.x;
    const int w   = tid >> 5;
    const int L   = tid & 31;

    if (tid < FF) sX[tid] = x[tid * BB + b];
    if (tid < KK) {
        sPooled[tid] = 0.f;
        sAth[tid]    = at_h[tid];
        sAb[tid]     = at_b[tid];
        sP[tid]      = pvec[tid];
    }
    for (int pp = tid; pp < SLOTS; pp += NTHREADS) {
        if (pp < NPAIR) {
            int i = 0, rem = pp;
            while (rem >= FF - 1 - i) { rem -= FF - 1 - i; i++; }
            sPi[pp] = (unsigned char)i;
            sPj[pp] = (unsigned char)(i + 1 + rem);
        } else { sPi[pp] = 0; sPj[pp] = 0; }
    }
    for (int idx = tid; idx < KK * HH; idx += NTHREADS)
        (&sW[0][0])[idx] = at_w[idx];
    __syncthreads();

    // gather embedding rows; consecutive tid -> consecutive k (coalesced)
    for (int idx = tid; idx < FF * KK; idx += NTHREADS) {
        int f = idx >> 6, k = idx & 63;
        sV[f][k] = emb[(long)sX[f] * KK + k];
    }
    __syncthreads();

    // first-order FM part
    if (w == 0) {
        float v = w1[sX[L]];
        #pragma unroll
        for (int off = 16; off; off >>= 1) v += __shfl_xor_sync(0xffffffffu, v, off);
        if (L == 0) sFm1 = v + w0[0];
    }

    const float2 bv = *(const float2*)&sAb[2 * L];
    const float2 av = *(const float2*)&sAth[2 * L];
    float pooled0 = 0.f, pooled1 = 0.f;
    const int base = w * SLOTS_PER_WARP;

    float4* const vvW = (float4*)sVVt[w];          // 64 float4s, 16B-aligned
    const float4* const vkp = (const float4*)sVVt[w];

    for (int g0 = 0; g0 < SLOTS_PER_WARP; g0 += 4) {
        float vvA[4], vvB[4];
        #pragma unroll
        for (int pr = 0; pr < 4; pr++) {
            int p = base + g0 + pr;
            int i = sPi[p], j = sPj[p];
            vvA[pr] = sV[i][L]      * sV[j][L];
            vvB[pr] = sV[i][L + 32] * sV[j][L + 32];
        }
        // pair-minor staging: row k holds {vv[p0],vv[p1],vv[p2],vv[p3]}
        vvW[L]      = make_float4(vvA[0], vvA[1], vvA[2], vvA[3]);
        vvW[L + 32] = make_float4(vvB[0], vvB[1], vvB[2], vvB[3]);
        __syncwarp();

        // hid = relu(VV @ W + b): lane owns columns h = 2L, 2L+1, 4 pairs at once
        float2 acc0 = {0.f,0.f}, acc1 = {0.f,0.f}, acc2 = {0.f,0.f}, acc3 = {0.f,0.f};
        #pragma unroll
        for (int k = 0; k < KK; k++) {
            float4 vk = vkp[k];                       // 1 broadcast LDS.128
            float2 wv = *(const float2*)&sW[k][2 * L];// 1 LDS.64
            acc0.x = fmaf(vk.x, wv.x, acc0.x); acc0.y = fmaf(vk.x, wv.y, acc0.y);
            acc1.x = fmaf(vk.y, wv.x, acc1.x); acc1.y = fmaf(vk.y, wv.y, acc1.y);
            acc2.x = fmaf(vk.z, wv.x, acc2.x); acc2.y = fmaf(vk.z, wv.y, acc2.y);
            acc3.x = fmaf(vk.w, wv.x, acc3.x); acc3.y = fmaf(vk.w, wv.y, acc3.y);
        }

        float part[4];
        {
            float h0, h1;
            h0 = fmaxf(acc0.x + bv.x, 0.f); h1 = fmaxf(acc0.y + bv.y, 0.f);
            part[0] = h0 * av.x + h1 * av.y;
            h0 = fmaxf(acc1.x + bv.x, 0.f); h1 = fmaxf(acc1.y + bv.y, 0.f);
            part[1] = h0 * av.x + h1 * av.y;
            h0 = fmaxf(acc2.x + bv.x, 0.f); h1 = fmaxf(acc2.y + bv.y, 0.f);
            part[2] = h0 * av.x + h1 * av.y;
            h0 = fmaxf(acc3.x + bv.x, 0.f); h1 = fmaxf(acc3.y + bv.y, 0.f);
            part[3] = h0 * av.x + h1 * av.y;
        }
        #pragma unroll
        for (int off = 16; off; off >>= 1) {
            #pragma unroll
            for (int pr = 0; pr < 4; pr++)
                part[pr] += __shfl_xor_sync(0xffffffffu, part[pr], off);
        }
        #pragma unroll
        for (int pr = 0; pr < 4; pr++) {
            int p   = base + g0 + pr;
            float s = (p < NPAIR) ? part[pr] : 0.f;   // kill padded slots
            pooled0 = fmaf(vvA[pr], s, pooled0);
            pooled1 = fmaf(vvB[pr], s, pooled1);
        }
        __syncwarp();   // protect sVVt before next group's writes
    }

    atomicAdd(&sPooled[L],      pooled0);
    atomicAdd(&sPooled[L + 32], pooled1);
    __syncthreads();

    if (w == 0) {
        float d = sPooled[L] * sP[L] + sPooled[L + 32] * sP[L + 32];
        #pragma unroll
        for (int off = 16; off; off >>= 1) d += __shfl_xor_sync(0xffffffffu, d, off);
        if (L == 0) {
            float logit = d + sFm1;
            out[b] = 1.f / (1.f + expf(-logit));
        }
    }
}

extern "C" void kernel_launch(void* const* d_in, const int* in_sizes, int n_in,
                              void* d_out, int out_size) {
    (void)in_sizes; (void)n_in; (void)out_size;
    const int*   x    = (const int*)  d_in[0];
    const float* emb  = (const float*)d_in[1];
    const float* at_w = (const float*)d_in[2];
    const float* at_b = (const float*)d_in[3];
    const float* at_h = (const float*)d_in[4];
    const float* pvec = (const float*)d_in[5];
    const float* w0   = (const float*)d_in[6];
    const float* w1   = (const float*)d_in[7];
    float* out = (float*)d_out;

    afm_kernel<<<BB, NTHREADS>>>(x, emb, at_w, at_b, at_h, pvec, w0, w1, out);
}

// round 6
// speedup vs baseline: 3.2808x; 3.2656x over previous
#include <cuda_runtime.h>
#include <cuda_bf16.h>
#include <stdint.h>
#include <math.h>

#define FF 32
#define BB 2048
#define KK 64
#define HH 64
#define NPAIR 496
#define NTHREADS 256
#define NWARP 8
#define SLOTS 512
#define VPAD 68   // sV row stride in floats (bank shift of 4 per row)

__device__ __forceinline__ void ldsm_x4_trans(unsigned& r0, unsigned& r1,
                                              unsigned& r2, unsigned& r3,
                                              unsigned addr)
{
    asm volatile(
        "ldmatrix.sync.aligned.m8n8.x4.trans.shared.b16 {%0,%1,%2,%3}, [%4];\n"
        : "=r"(r0), "=r"(r1), "=r"(r2), "=r"(r3) : "r"(addr));
}

__device__ __forceinline__ void mma_bf16_16x8x16(float* c,
                                                 unsigned a0, unsigned a1,
                                                 unsigned a2, unsigned a3,
                                                 unsigned b0, unsigned b1)
{
    asm volatile(
        "mma.sync.aligned.m16n8k16.row.col.f32.bf16.bf16.f32 "
        "{%0,%1,%2,%3}, {%4,%5,%6,%7}, {%8,%9}, {%0,%1,%2,%3};\n"
        : "+f"(c[0]), "+f"(c[1]), "+f"(c[2]), "+f"(c[3])
        : "r"(a0), "r"(a1), "r"(a2), "r"(a3), "r"(b0), "r"(b1));
}

__device__ __forceinline__ unsigned pack_bf16x2(float lo, float hi)
{
    __nv_bfloat162 t2 = __floats2bfloat162_rn(lo, hi);
    return *(unsigned*)&t2;
}

__global__ __launch_bounds__(NTHREADS) void afm_kernel(
    const int* __restrict__ x, const float* __restrict__ emb,
    const float* __restrict__ at_w, const float* __restrict__ at_b,
    const float* __restrict__ at_h, const float* __restrict__ pvec,
    const float* __restrict__ w0, const float* __restrict__ w1,
    float* __restrict__ out)
{
    __shared__ float sV[FF][VPAD];                       // ~8.7 KB
    __shared__ __align__(16) __nv_bfloat16 sWb[KK * HH]; // 8 KB, XOR-swizzled
    __shared__ float sAth[HH];
    __shared__ float sAb[HH];
    __shared__ float sP[KK];
    __shared__ float sPooled[KK];
    __shared__ float sScore[SLOTS];
    __shared__ int   sX[FF];
    __shared__ unsigned char sPi[SLOTS], sPj[SLOTS];
    __shared__ float sFm1;

    const int b   = blockIdx.x;
    const int tid = threadIdx.x;
    const int w   = tid >> 5;
    const int L   = tid & 31;

    if (tid < FF) sX[tid] = x[tid * BB + b];
    if (tid < KK) {
        sPooled[tid] = 0.f;
        sAth[tid]    = at_h[tid];
        sAb[tid]     = at_b[tid];
        sP[tid]      = pvec[tid];
    }
    // pair-index table, padded to 512 slots
    for (int pp = tid; pp < SLOTS; pp += NTHREADS) {
        if (pp < NPAIR) {
            int i = 0, rem = pp;
            while (rem >= FF - 1 - i) { rem -= FF - 1 - i; i++; }
            sPi[pp] = (unsigned char)i;
            sPj[pp] = (unsigned char)(i + 1 + rem);
        } else { sPi[pp] = 0; sPj[pp] = 0; }
    }
    // at_w -> bf16, swizzled: (k,h) stored at element k*64 + ((h/8 ^ (k&7))*8) + (h&7)
    for (int idx = tid; idx < KK * HH; idx += NTHREADS) {
        int k = idx >> 6, h = idx & 63;
        int chunk = (h >> 3) ^ (k & 7);
        sWb[k * 64 + chunk * 8 + (h & 7)] = __float2bfloat16(at_w[idx]);
    }
    __syncthreads();

    // gather embedding rows (coalesced along k)
    for (int idx = tid; idx < FF * KK; idx += NTHREADS) {
        int f = idx >> 6, k = idx & 63;
        sV[f][k] = emb[(long)sX[f] * KK + k];
    }
    __syncthreads();

    // first-order FM part
    if (w == 0) {
        float v = w1[sX[L]];
        #pragma unroll
        for (int off = 16; off; off >>= 1) v += __shfl_xor_sync(0xffffffffu, v, off);
        if (L == 0) sFm1 = v + w0[0];
    }

    const unsigned swb_base = (unsigned)__cvta_generic_to_shared(sWb);
    const int qr  = L >> 2;        // 0..7  fragment row within 8
    const int qc2 = (L & 3) << 1;  // 0,2,4,6 fragment col pair
    const int sub = L >> 3;        // ldmatrix sub-block 0..3
    const int lr  = L & 7;

    // ---- MMA phase: hid = relu(VV @ W + b); score = hid . at_h ------------
    #pragma unroll
    for (int it = 0; it < 4; it++) {
        const int mbase = (w * 4 + it) << 4;          // 16 pairs per m-tile
        const int p0 = mbase + qr, p1 = p0 + 8;
        const int i0 = sPi[p0], j0 = sPj[p0];
        const int i1 = sPi[p1], j1 = sPj[p1];

        float acc[8][4];
        #pragma unroll
        for (int t = 0; t < 8; t++)
            acc[t][0] = acc[t][1] = acc[t][2] = acc[t][3] = 0.f;

        #pragma unroll
        for (int ks = 0; ks < 4; ks++) {
            const int k0 = (ks << 4) + qc2;
            unsigned fa0, fa1, fa2, fa3;
            {
                float2 vi, vj;
                vi = *(const float2*)&sV[i0][k0];
                vj = *(const float2*)&sV[j0][k0];
                fa0 = pack_bf16x2(vi.x * vj.x, vi.y * vj.y);
                vi = *(const float2*)&sV[i1][k0];
                vj = *(const float2*)&sV[j1][k0];
                fa1 = pack_bf16x2(vi.x * vj.x, vi.y * vj.y);
                vi = *(const float2*)&sV[i0][k0 + 8];
                vj = *(const float2*)&sV[j0][k0 + 8];
                fa2 = pack_bf16x2(vi.x * vj.x, vi.y * vj.y);
                vi = *(const float2*)&sV[i1][k0 + 8];
                vj = *(const float2*)&sV[j1][k0 + 8];
                fa3 = pack_bf16x2(vi.x * vj.x, vi.y * vj.y);
            }

            const int krow = (ks << 4) + ((sub & 1) << 3) + lr;
            #pragma unroll
            for (int tp = 0; tp < 4; tp++) {
                int chunk = (tp << 1) + (sub >> 1);
                unsigned maddr = swb_base + (unsigned)(krow * 128)
                               + (unsigned)(((chunk ^ (krow & 7))) << 4);
                unsigned fb0, fb1, fb2, fb3;
                ldsm_x4_trans(fb0, fb1, fb2, fb3, maddr);
                mma_bf16_16x8x16(acc[tp * 2],     fa0, fa1, fa2, fa3, fb0, fb1);
                mma_bf16_16x8x16(acc[tp * 2 + 1], fa0, fa1, fa2, fa3, fb2, fb3);
            }
        }

        // epilogue: score[p] = sum_h relu(hid + b) * at_h
        float s0 = 0.f, s1 = 0.f;
        #pragma unroll
        for (int t = 0; t < 8; t++) {
            int h0 = (t << 3) + qc2;
            float2 ab = *(const float2*)&sAb[h0];
            float2 ah = *(const float2*)&sAth[h0];
            s0 += fmaxf(acc[t][0] + ab.x, 0.f) * ah.x
                + fmaxf(acc[t][1] + ab.y, 0.f) * ah.y;
            s1 += fmaxf(acc[t][2] + ab.x, 0.f) * ah.x
                + fmaxf(acc[t][3] + ab.y, 0.f) * ah.y;
        }
        s0 += __shfl_xor_sync(0xffffffffu, s0, 1);
        s0 += __shfl_xor_sync(0xffffffffu, s0, 2);
        s1 += __shfl_xor_sync(0xffffffffu, s1, 1);
        s1 += __shfl_xor_sync(0xffffffffu, s1, 2);
        if ((L & 3) == 0) {
            sScore[p0] = (p0 < NPAIR) ? s0 : 0.f;
            sScore[p1] = (p1 < NPAIR) ? s1 : 0.f;
        }
    }
    __syncthreads();

    // ---- pooling: pooled[k] = sum_p VV[p,k] * score[p]  (fp32 VV) ----------
    float pooled0 = 0.f, pooled1 = 0.f;
    const int base = w << 6;
    #pragma unroll 4
    for (int g = 0; g < 64; g++) {
        int p = base + g;
        float s = sScore[p];
        int i = sPi[p], j = sPj[p];
        pooled0 = fmaf(sV[i][L]      * sV[j][L],      s, pooled0);
        pooled1 = fmaf(sV[i][L + 32] * sV[j][L + 32], s, pooled1);
    }
    atomicAdd(&sPooled[L],      pooled0);
    atomicAdd(&sPooled[L + 32], pooled1);
    __syncthreads();

    if (w == 0) {
        float d = sPooled[L] * sP[L] + sPooled[L + 32] * sP[L + 32];
        #pragma unroll
        for (int off = 16; off; off >>= 1) d += __shfl_xor_sync(0xffffffffu, d, off);
        if (L == 0) {
            float logit = d + sFm1;
            out[b] = 1.f / (1.f + expf(-logit));
        }
    }
}

extern "C" void kernel_launch(void* const* d_in, const int* in_sizes, int n_in,
                              void* d_out, int out_size) {
    (void)in_sizes; (void)n_in; (void)out_size;
    const int*   x    = (const int*)  d_in[0];
    const float* emb  = (const float*)d_in[1];
    const float* at_w = (const float*)d_in[2];
    const float* at_b = (const float*)d_in[3];
    const float* at_h = (const float*)d_in[4];
    const float* pvec = (const float*)d_in[5];
    const float* w0   = (const float*)d_in[6];
    const float* w1   = (const float*)d_in[7];
    float* out = (float*)d_out;

    afm_kernel<<<BB, NTHREADS>>>(x, emb, at_w, at_b, at_h, pvec, w0, w1, out);
}

// round 7
// speedup vs baseline: 3.8089x; 1.1610x over previous
#include <cuda_runtime.h>
#include <cuda_bf16.h>
#include <stdint.h>
#include <math.h>

#define FF 32
#define BB 2048
#define KK 64
#define HH 64
#define NPAIR 496
#define NTHREADS 256
#define NWARP 8
#define SLOTS 512
#define VSTRIDE 66   // bf16 elems per sV row: 132B -> bank = (i + c) mod 32, conflict-free

__device__ __forceinline__ void ldsm_x4_trans(unsigned& r0, unsigned& r1,
                                              unsigned& r2, unsigned& r3,
                                              unsigned addr)
{
    asm volatile(
        "ldmatrix.sync.aligned.m8n8.x4.trans.shared.b16 {%0,%1,%2,%3}, [%4];\n"
        : "=r"(r0), "=r"(r1), "=r"(r2), "=r"(r3) : "r"(addr));
}

__device__ __forceinline__ void mma_bf16_16x8x16(float* c,
                                                 unsigned a0, unsigned a1,
                                                 unsigned a2, unsigned a3,
                                                 unsigned b0, unsigned b1)
{
    asm volatile(
        "mma.sync.aligned.m16n8k16.row.col.f32.bf16.bf16.f32 "
        "{%0,%1,%2,%3}, {%4,%5,%6,%7}, {%8,%9}, {%0,%1,%2,%3};\n"
        : "+f"(c[0]), "+f"(c[1]), "+f"(c[2]), "+f"(c[3])
        : "r"(a0), "r"(a1), "r"(a2), "r"(a3), "r"(b0), "r"(b1));
}

__device__ __forceinline__ unsigned hmul2u(unsigned a, unsigned b)
{
    __nv_bfloat162 r = __hmul2(*(__nv_bfloat162*)&a, *(__nv_bfloat162*)&b);
    return *(unsigned*)&r;
}

__global__ __launch_bounds__(NTHREADS) void afm_kernel(
    const int* __restrict__ x, const float* __restrict__ emb,
    const float* __restrict__ at_w, const float* __restrict__ at_b,
    const float* __restrict__ at_h, const float* __restrict__ pvec,
    const float* __restrict__ w0, const float* __restrict__ w1,
    float* __restrict__ out)
{
    __shared__ __align__(16) __nv_bfloat16 sVb[FF * VSTRIDE];   // ~4.1 KB
    __shared__ __align__(16) __nv_bfloat16 sWb[KK * HH];        // 8 KB, XOR-swizzled
    __shared__ float sAth[HH];
    __shared__ float sAb[HH];
    __shared__ float sP[KK];
    __shared__ float sPooled[KK];
    __shared__ __align__(16) float sScore[SLOTS];
    __shared__ __align__(16) unsigned sPij[SLOTS];  // (rowOffJ<<16)|rowOffI, elem offsets
    __shared__ int   sX[FF];
    __shared__ float sFm1;

    const int b   = blockIdx.x;
    const int tid = threadIdx.x;
    const int w   = tid >> 5;
    const int L   = tid & 31;

    if (tid < FF) sX[tid] = x[tid * BB + b];
    if (tid < KK) {
        sPooled[tid] = 0.f;
        sAth[tid]    = at_h[tid];
        sAb[tid]     = at_b[tid];
        sP[tid]      = pvec[tid];
    }
    // pair table: packed row element-offsets, padded to 512 slots
    for (int pp = tid; pp < SLOTS; pp += NTHREADS) {
        unsigned v = 0;
        if (pp < NPAIR) {
            int i = 0, rem = pp;
            while (rem >= FF - 1 - i) { rem -= FF - 1 - i; i++; }
            int j = i + 1 + rem;
            v = ((unsigned)(j * VSTRIDE) << 16) | (unsigned)(i * VSTRIDE);
        }
        sPij[pp] = v;
    }
    // at_w -> bf16, swizzled: (k,h) at element k*64 + ((h/8 ^ (k&7))*8) + (h&7)
    for (int idx = tid; idx < KK * HH; idx += NTHREADS) {
        int k = idx >> 6, h = idx & 63;
        int chunk = (h >> 3) ^ (k & 7);
        sWb[k * 64 + chunk * 8 + (h & 7)] = __float2bfloat16(at_w[idx]);
    }
    __syncthreads();

    // gather embedding rows -> bf16 (coalesced along k)
    for (int idx = tid; idx < FF * KK; idx += NTHREADS) {
        int f = idx >> 6, k = idx & 63;
        sVb[f * VSTRIDE + k] = __float2bfloat16(emb[(long)sX[f] * KK + k]);
    }
    __syncthreads();

    // first-order FM part
    if (w == 0) {
        float v = w1[sX[L]];
        #pragma unroll
        for (int off = 16; off; off >>= 1) v += __shfl_xor_sync(0xffffffffu, v, off);
        if (L == 0) sFm1 = v + w0[0];
    }

    const unsigned swb_base = (unsigned)__cvta_generic_to_shared(sWb);
    const __nv_bfloat16* const vb = sVb;
    const int qr  = L >> 2;        // 0..7 fragment row within 8
    const int qc2 = (L & 3) << 1;  // 0,2,4,6 fragment col pair
    const int sub = L >> 3;        // ldmatrix sub-block 0..3
    const int lr  = L & 7;

    // ---- MMA phase: hid = relu(VV @ W + b); score = hid . at_h ------------
    #pragma unroll
    for (int it = 0; it < 4; it++) {
        const int mbase = (w * 4 + it) << 4;          // 16 pairs per m-tile
        const int p0 = mbase + qr, p1 = p0 + 8;
        const unsigned pij0 = sPij[p0], pij1 = sPij[p1];
        const int eI0 = pij0 & 0xffffu, eJ0 = pij0 >> 16;
        const int eI1 = pij1 & 0xffffu, eJ1 = pij1 >> 16;

        float acc[8][4];
        #pragma unroll
        for (int t = 0; t < 8; t++)
            acc[t][0] = acc[t][1] = acc[t][2] = acc[t][3] = 0.f;

        #pragma unroll
        for (int ks = 0; ks < 4; ks++) {
            const int k0 = (ks << 4) + qc2;
            // A fragments: bf16x2 loads + HMUL2 (conflict-free / broadcast)
            unsigned fa0 = hmul2u(*(const unsigned*)&vb[eI0 + k0],
                                  *(const unsigned*)&vb[eJ0 + k0]);
            unsigned fa1 = hmul2u(*(const unsigned*)&vb[eI1 + k0],
                                  *(const unsigned*)&vb[eJ1 + k0]);
            unsigned fa2 = hmul2u(*(const unsigned*)&vb[eI0 + k0 + 8],
                                  *(const unsigned*)&vb[eJ0 + k0 + 8]);
            unsigned fa3 = hmul2u(*(const unsigned*)&vb[eI1 + k0 + 8],
                                  *(const unsigned*)&vb[eJ1 + k0 + 8]);

            const int krow = (ks << 4) + ((sub & 1) << 3) + lr;
            #pragma unroll
            for (int tp = 0; tp < 4; tp++) {
                int chunk = (tp << 1) + (sub >> 1);
                unsigned maddr = swb_base + (unsigned)(krow * 128)
                               + (unsigned)(((chunk ^ (krow & 7))) << 4);
                unsigned fb0, fb1, fb2, fb3;
                ldsm_x4_trans(fb0, fb1, fb2, fb3, maddr);
                mma_bf16_16x8x16(acc[tp * 2],     fa0, fa1, fa2, fa3, fb0, fb1);
                mma_bf16_16x8x16(acc[tp * 2 + 1], fa0, fa1, fa2, fa3, fb2, fb3);
            }
        }

        // epilogue: score[p] = sum_h relu(hid + b) * at_h
        float s0 = 0.f, s1 = 0.f;
        #pragma unroll
        for (int t = 0; t < 8; t++) {
            int h0 = (t << 3) + qc2;
            float2 ab = *(const float2*)&sAb[h0];
            float2 ah = *(const float2*)&sAth[h0];
            s0 += fmaxf(acc[t][0] + ab.x, 0.f) * ah.x
                + fmaxf(acc[t][1] + ab.y, 0.f) * ah.y;
            s1 += fmaxf(acc[t][2] + ab.x, 0.f) * ah.x
                + fmaxf(acc[t][3] + ab.y, 0.f) * ah.y;
        }
        s0 += __shfl_xor_sync(0xffffffffu, s0, 1);
        s0 += __shfl_xor_sync(0xffffffffu, s0, 2);
        s1 += __shfl_xor_sync(0xffffffffu, s1, 1);
        s1 += __shfl_xor_sync(0xffffffffu, s1, 2);
        if ((L & 3) == 0) {
            sScore[p0] = (p0 < NPAIR) ? s0 : 0.f;
            sScore[p1] = (p1 < NPAIR) ? s1 : 0.f;
        }
    }
    __syncthreads();

    // ---- pooling: pooled[k] = sum_p VV[p,k]*score[p]; lane owns k=2L,2L+1 --
    float pooled0 = 0.f, pooled1 = 0.f;
    const int base = w << 6;
    const int kb = L << 1;   // element offset of this lane's k-pair
    #pragma unroll 4
    for (int g4 = 0; g4 < 64; g4 += 4) {
        float4 sc  = *(const float4*)&sScore[base + g4];   // broadcast
        uint4  pj4 = *(const uint4*)&sPij[base + g4];      // broadcast
        unsigned pw[4] = {pj4.x, pj4.y, pj4.z, pj4.w};
        float sv[4] = {sc.x, sc.y, sc.z, sc.w};
        #pragma unroll
        for (int r = 0; r < 4; r++) {
            int eI = pw[r] & 0xffffu, eJ = pw[r] >> 16;
            unsigned prod = hmul2u(*(const unsigned*)&vb[eI + kb],
                                   *(const unsigned*)&vb[eJ + kb]);
            float2 pf = __bfloat1622float2(*(__nv_bfloat162*)&prod);
            pooled0 = fmaf(pf.x, sv[r], pooled0);
            pooled1 = fmaf(pf.y, sv[r], pooled1);
        }
    }
    atomicAdd(&sPooled[kb],     pooled0);
    atomicAdd(&sPooled[kb + 1], pooled1);
    __syncthreads();

    if (w == 0) {
        float d = sPooled[kb] * sP[kb] + sPooled[kb + 1] * sP[kb + 1];
        #pragma unroll
        for (int off = 16; off; off >>= 1) d += __shfl_xor_sync(0xffffffffu, d, off);
        if (L == 0) {
            float logit = d + sFm1;
            out[b] = 1.f / (1.f + expf(-logit));
        }
    }
}

extern "C" void kernel_launch(void* const* d_in, const int* in_sizes, int n_in,
                              void* d_out, int out_size) {
    (void)in_sizes; (void)n_in; (void)out_size;
    const int*   x    = (const int*)  d_in[0];
    const float* emb  = (const float*)d_in[1];
    const float* at_w = (const float*)d_in[2];
    const float* at_b = (const float*)d_in[3];
    const float* at_h = (const float*)d_in[4];
    const float* pvec = (const float*)d_in[5];
    const float* w0   = (const float*)d_in[6];
    const float* w1   = (const float*)d_in[7];
    float* out = (float*)d_out;

    afm_kernel<<<BB, NTHREADS>>>(x, emb, at_w, at_b, at_h, pvec, w0, w1, out);
}

// round 8
// speedup vs baseline: 3.9780x; 1.0444x over previous
#include <cuda_runtime.h>
#include <cuda_bf16.h>
#include <stdint.h>
#include <math.h>

#define FF 32
#define BB 2048
#define KK 64
#define HH 64
#define NPAIR 496
#define NTHREADS 256
#define NWARP 8
#define SLOTS 512
#define VSTRIDE 66   // bf16 elems per sV row: 132B -> conflict-free row banking

__device__ __forceinline__ void ldsm_x4_trans(unsigned& r0, unsigned& r1,
                                              unsigned& r2, unsigned& r3,
                                              unsigned addr)
{
    asm volatile(
        "ldmatrix.sync.aligned.m8n8.x4.trans.shared.b16 {%0,%1,%2,%3}, [%4];\n"
        : "=r"(r0), "=r"(r1), "=r"(r2), "=r"(r3) : "r"(addr));
}

__device__ __forceinline__ void mma_bf16_16x8x16(float* c,
                                                 unsigned a0, unsigned a1,
                                                 unsigned a2, unsigned a3,
                                                 unsigned b0, unsigned b1)
{
    asm volatile(
        "mma.sync.aligned.m16n8k16.row.col.f32.bf16.bf16.f32 "
        "{%0,%1,%2,%3}, {%4,%5,%6,%7}, {%8,%9}, {%0,%1,%2,%3};\n"
        : "+f"(c[0]), "+f"(c[1]), "+f"(c[2]), "+f"(c[3])
        : "r"(a0), "r"(a1), "r"(a2), "r"(a3), "r"(b0), "r"(b1));
}

__device__ __forceinline__ unsigned hmul2u(unsigned a, unsigned b)
{
    __nv_bfloat162 r = __hmul2(*(__nv_bfloat162*)&a, *(__nv_bfloat162*)&b);
    return *(unsigned*)&r;
}

__global__ __launch_bounds__(NTHREADS, 5) void afm_kernel(
    const int* __restrict__ x, const float* __restrict__ emb,
    const float* __restrict__ at_w, const float* __restrict__ at_b,
    const float* __restrict__ at_h, const float* __restrict__ pvec,
    const float* __restrict__ w0, const float* __restrict__ w1,
    float* __restrict__ out)
{
    __shared__ __align__(16) __nv_bfloat16 sVb[FF * VSTRIDE];   // ~4.1 KB
    __shared__ __align__(16) __nv_bfloat16 sWb[KK * HH];        // 8 KB, XOR-swizzled
    __shared__ float sAth[HH];
    __shared__ float sAb[HH];
    __shared__ float sP[KK];
    __shared__ float sPooled[KK];
    __shared__ __align__(16) float sScore[SLOTS];
    __shared__ __align__(16) unsigned sPij[SLOTS];  // (rowOffJ<<16)|rowOffI
    __shared__ int   sX[FF];
    __shared__ float sFm1;

    const int b   = blockIdx.x;
    const int tid = threadIdx.x;
    const int w   = tid >> 5;
    const int L   = tid & 31;

    if (tid < FF) sX[tid] = x[tid * BB + b];
    if (tid < KK) {
        sPooled[tid] = 0.f;
        sAth[tid]    = at_h[tid];
        sAb[tid]     = at_b[tid];
        sP[tid]      = pvec[tid];
    }
    for (int pp = tid; pp < SLOTS; pp += NTHREADS) {
        unsigned v = 0;
        if (pp < NPAIR) {
            int i = 0, rem = pp;
            while (rem >= FF - 1 - i) { rem -= FF - 1 - i; i++; }
            int j = i + 1 + rem;
            v = ((unsigned)(j * VSTRIDE) << 16) | (unsigned)(i * VSTRIDE);
        }
        sPij[pp] = v;
    }
    // at_w -> bf16, swizzled: (k,h) at element k*64 + ((h/8 ^ (k&7))*8) + (h&7)
    for (int idx = tid; idx < KK * HH; idx += NTHREADS) {
        int k = idx >> 6, h = idx & 63;
        int chunk = (h >> 3) ^ (k & 7);
        sWb[k * 64 + chunk * 8 + (h & 7)] = __float2bfloat16(at_w[idx]);
    }
    __syncthreads();

    // gather embedding rows -> bf16 (coalesced along k)
    for (int idx = tid; idx < FF * KK; idx += NTHREADS) {
        int f = idx >> 6, k = idx & 63;
        sVb[f * VSTRIDE + k] = __float2bfloat16(emb[(long)sX[f] * KK + k]);
    }
    __syncthreads();

    // first-order FM part
    if (w == 0) {
        float v = w1[sX[L]];
        #pragma unroll
        for (int off = 16; off; off >>= 1) v += __shfl_xor_sync(0xffffffffu, v, off);
        if (L == 0) sFm1 = v + w0[0];
    }

    const unsigned swb_base = (unsigned)__cvta_generic_to_shared(sWb);
    const __nv_bfloat16* const vb = sVb;
    const int qr  = L >> 2;        // 0..7 fragment row within 8
    const int qc2 = (L & 3) << 1;  // 0,2,4,6 fragment col pair
    const int sub = L >> 3;        // ldmatrix sub-block 0..3
    const int lr  = L & 7;

    // hoisted ldsm addresses: krow = ks*16 + (sub&1)*8 + lr, krow&7 == lr
    // maddr(ks,tp) = base_tp[tp] + ks*2048
    unsigned base_tp[4];
    {
        unsigned row_base = swb_base + (unsigned)((((sub & 1) << 3) + lr) * 128);
        #pragma unroll
        for (int tp = 0; tp < 4; tp++)
            base_tp[tp] = row_base
                        + (unsigned)((((tp << 1) + (sub >> 1)) ^ lr) << 4);
    }

    // ---- MMA phase: hid = relu(VV @ W + b); score = hid . at_h ------------
    #pragma unroll 1
    for (int it = 0; it < 4; it++) {
        const int mbase = (w * 4 + it) << 4;          // 16 pairs per m-tile
        const int p0 = mbase + qr, p1 = p0 + 8;
        const unsigned pij0 = sPij[p0], pij1 = sPij[p1];
        const int eI0 = pij0 & 0xffffu, eJ0 = pij0 >> 16;
        const int eI1 = pij1 & 0xffffu, eJ1 = pij1 >> 16;

        // preload all A fragments for this m-tile (16 regs)
        unsigned fa[4][4];
        #pragma unroll
        for (int ks = 0; ks < 4; ks++) {
            const int k0 = (ks << 4) + qc2;
            fa[ks][0] = hmul2u(*(const unsigned*)&vb[eI0 + k0],
                               *(const unsigned*)&vb[eJ0 + k0]);
            fa[ks][1] = hmul2u(*(const unsigned*)&vb[eI1 + k0],
                               *(const unsigned*)&vb[eJ1 + k0]);
            fa[ks][2] = hmul2u(*(const unsigned*)&vb[eI0 + k0 + 8],
                               *(const unsigned*)&vb[eJ0 + k0 + 8]);
            fa[ks][3] = hmul2u(*(const unsigned*)&vb[eI1 + k0 + 8],
                               *(const unsigned*)&vb[eJ1 + k0 + 8]);
        }

        float s0 = 0.f, s1 = 0.f;
        #pragma unroll
        for (int tp = 0; tp < 4; tp++) {
            float acc2[2][4];
            #pragma unroll
            for (int u = 0; u < 2; u++)
                acc2[u][0] = acc2[u][1] = acc2[u][2] = acc2[u][3] = 0.f;

            #pragma unroll
            for (int ks = 0; ks < 4; ks++) {
                unsigned maddr = base_tp[tp] + (unsigned)(ks << 11);
                unsigned fb0, fb1, fb2, fb3;
                ldsm_x4_trans(fb0, fb1, fb2, fb3, maddr);
                mma_bf16_16x8x16(acc2[0], fa[ks][0], fa[ks][1], fa[ks][2], fa[ks][3], fb0, fb1);
                mma_bf16_16x8x16(acc2[1], fa[ks][0], fa[ks][1], fa[ks][2], fa[ks][3], fb2, fb3);
            }

            // incremental epilogue: h-chunks t = 2tp, 2tp+1
            #pragma unroll
            for (int u = 0; u < 2; u++) {
                int h0 = (((tp << 1) + u) << 3) + qc2;
                float2 ab = *(const float2*)&sAb[h0];
                float2 ah = *(const float2*)&sAth[h0];
                s0 += fmaxf(acc2[u][0] + ab.x, 0.f) * ah.x
                    + fmaxf(acc2[u][1] + ab.y, 0.f) * ah.y;
                s1 += fmaxf(acc2[u][2] + ab.x, 0.f) * ah.x
                    + fmaxf(acc2[u][3] + ab.y, 0.f) * ah.y;
            }
        }

        s0 += __shfl_xor_sync(0xffffffffu, s0, 1);
        s0 += __shfl_xor_sync(0xffffffffu, s0, 2);
        s1 += __shfl_xor_sync(0xffffffffu, s1, 1);
        s1 += __shfl_xor_sync(0xffffffffu, s1, 2);
        if ((L & 3) == 0) {
            sScore[p0] = (p0 < NPAIR) ? s0 : 0.f;
            sScore[p1] = (p1 < NPAIR) ? s1 : 0.f;
        }
    }
    __syncthreads();

    // ---- pooling: pooled[k] = sum_p VV[p,k]*score[p]; lane owns k=2L,2L+1 --
    float pooled0 = 0.f, pooled1 = 0.f;
    const int base = w << 6;
    const int kb = L << 1;
    #pragma unroll 4
    for (int g4 = 0; g4 < 64; g4 += 4) {
        float4 sc  = *(const float4*)&sScore[base + g4];   // broadcast
        uint4  pj4 = *(const uint4*)&sPij[base + g4];      // broadcast
        unsigned pw[4] = {pj4.x, pj4.y, pj4.z, pj4.w};
        float sv[4] = {sc.x, sc.y, sc.z, sc.w};
        #pragma unroll
        for (int r = 0; r < 4; r++) {
            int eI = pw[r] & 0xffffu, eJ = pw[r] >> 16;
            unsigned prod = hmul2u(*(const unsigned*)&vb[eI + kb],
                                   *(const unsigned*)&vb[eJ + kb]);
            float2 pf = __bfloat1622float2(*(__nv_bfloat162*)&prod);
            pooled0 = fmaf(pf.x, sv[r], pooled0);
            pooled1 = fmaf(pf.y, sv[r], pooled1);
        }
    }
    atomicAdd(&sPooled[kb],     pooled0);
    atomicAdd(&sPooled[kb + 1], pooled1);
    __syncthreads();

    if (w == 0) {
        float d = sPooled[kb] * sP[kb] + sPooled[kb + 1] * sP[kb + 1];
        #pragma unroll
        for (int off = 16; off; off >>= 1) d += __shfl_xor_sync(0xffffffffu, d, off);
        if (L == 0) {
            float logit = d + sFm1;
            out[b] = 1.f / (1.f + expf(-logit));
        }
    }
}

extern "C" void kernel_launch(void* const* d_in, const int* in_sizes, int n_in,
                              void* d_out, int out_size) {
    (void)in_sizes; (void)n_in; (void)out_size;
    const int*   x    = (const int*)  d_in[0];
    const float* emb  = (const float*)d_in[1];
    const float* at_w = (const float*)d_in[2];
    const float* at_b = (const float*)d_in[3];
    const float* at_h = (const float*)d_in[4];
    const float* pvec = (const float*)d_in[5];
    const float* w0   = (const float*)d_in[6];
    const float* w1   = (const float*)d_in[7];
    float* out = (float*)d_out;

    afm_kernel<<<BB, NTHREADS>>>(x, emb, at_w, at_b, at_h, pvec, w0, w1, out);
}

// round 10
// speedup vs baseline: 4.2122x; 1.0589x over previous
#include <cuda_runtime.h>
#include <cuda_bf16.h>
#include <stdint.h>
#include <math.h>

#define FF 32
#define BB 2048
#define KK 64
#define HH 64
#define NPAIR 496
#define NTHREADS 256
#define NWARP 8
#define SLOTS 512
#define VSTRIDE 66   // bf16 elems per sV row: 132B -> conflict-free row banking

__device__ __align__(16) __nv_bfloat16 gWb[KK * HH];  // swizzled bf16 at_w
__device__ __align__(16) unsigned      gPij[SLOTS];   // (rowOffJ<<16)|rowOffI

__device__ __forceinline__ void ldsm_x4_trans(unsigned& r0, unsigned& r1,
                                              unsigned& r2, unsigned& r3,
                                              unsigned addr)
{
    asm volatile(
        "ldmatrix.sync.aligned.m8n8.x4.trans.shared.b16 {%0,%1,%2,%3}, [%4];\n"
        : "=r"(r0), "=r"(r1), "=r"(r2), "=r"(r3) : "r"(addr));
}

__device__ __forceinline__ void mma_bf16_16x8x16(float* c,
                                                 unsigned a0, unsigned a1,
                                                 unsigned a2, unsigned a3,
                                                 unsigned b0, unsigned b1)
{
    asm volatile(
        "mma.sync.aligned.m16n8k16.row.col.f32.bf16.bf16.f32 "
        "{%0,%1,%2,%3}, {%4,%5,%6,%7}, {%8,%9}, {%0,%1,%2,%3};\n"
        : "+f"(c[0]), "+f"(c[1]), "+f"(c[2]), "+f"(c[3])
        : "r"(a0), "r"(a1), "r"(a2), "r"(a3), "r"(b0), "r"(b1));
}

__device__ __forceinline__ unsigned hmul2u(unsigned a, unsigned b)
{
    __nv_bfloat162 r = __hmul2(*(__nv_bfloat162*)&a, *(__nv_bfloat162*)&b);
    return *(unsigned*)&r;
}

// One-shot per-launch precompute of block-invariant tables.
// grid 16x256 = 4096 threads: idx<4096 covers gWb, idx<512 covers gPij.
__global__ void afm_init(const float* __restrict__ at_w)
{
    int idx = blockIdx.x * blockDim.x + threadIdx.x;
    if (idx < KK * HH) {
        int k = idx >> 6, h = idx & 63;
        int chunk = (h >> 3) ^ (k & 7);
        gWb[k * 64 + chunk * 8 + (h & 7)] = __float2bfloat16(at_w[idx]);
    }
    if (idx < SLOTS) {
        unsigned v = 0;
        if (idx < NPAIR) {
            int i = 0, rem = idx;
            while (rem >= FF - 1 - i) { rem -= FF - 1 - i; i++; }
            int j = i + 1 + rem;
            v = ((unsigned)(j * VSTRIDE) << 16) | (unsigned)(i * VSTRIDE);
        }
        gPij[idx] = v;
    }
}

__global__ __launch_bounds__(NTHREADS, 5) void afm_kernel(
    const int* __restrict__ x, const float* __restrict__ emb,
    const float* __restrict__ at_b,
    const float* __restrict__ at_h, const float* __restrict__ pvec,
    const float* __restrict__ w0, const float* __restrict__ w1,
    float* __restrict__ out)
{
    __shared__ __align__(16) __nv_bfloat16 sVb[FF * VSTRIDE];   // ~4.1 KB
    __shared__ __align__(16) __nv_bfloat16 sWb[KK * HH];        // 8 KB, XOR-swizzled
    __shared__ float sAth[HH];
    __shared__ float sAb[HH];
    __shared__ float sP[KK];
    __shared__ float sPooled[KK];
    __shared__ __align__(16) float sScore[SLOTS];
    __shared__ __align__(16) unsigned sPij[SLOTS];
    __shared__ int   sX[FF];
    __shared__ float sFm1;

    const int b   = blockIdx.x;
    const int tid = threadIdx.x;
    const int w   = tid >> 5;
    const int L   = tid & 31;

    if (tid < FF) sX[tid] = x[tid * BB + b];
    if (tid < KK) {
        sPooled[tid] = 0.f;
        sAth[tid]    = at_h[tid];
        sAb[tid]     = at_b[tid];
        sP[tid]      = pvec[tid];
    }
    // vectorized copies of precomputed tables (L2-resident)
    ((uint2*)sPij)[tid] = ((const uint2*)gPij)[tid];          // 512 words
    ((uint4*)sWb)[tid]       = ((const uint4*)gWb)[tid];      // 8 KB total
    ((uint4*)sWb)[tid + 256] = ((const uint4*)gWb)[tid + 256];
    __syncthreads();

    // gather embedding rows -> bf16 (coalesced along k)
    for (int idx = tid; idx < FF * KK; idx += NTHREADS) {
        int f = idx >> 6, k = idx & 63;
        sVb[f * VSTRIDE + k] = __float2bfloat16(emb[(long)sX[f] * KK + k]);
    }
    __syncthreads();

    // first-order FM part
    if (w == 0) {
        float v = w1[sX[L]];
        #pragma unroll
        for (int off = 16; off; off >>= 1) v += __shfl_xor_sync(0xffffffffu, v, off);
        if (L == 0) sFm1 = v + w0[0];
    }

    const unsigned swb_base = (unsigned)__cvta_generic_to_shared(sWb);
    const __nv_bfloat16* const vb = sVb;
    const int qr  = L >> 2;        // 0..7 fragment row within 8
    const int qc2 = (L & 3) << 1;  // 0,2,4,6 fragment col pair
    const int sub = L >> 3;        // ldmatrix sub-block 0..3
    const int lr  = L & 7;

    // hoisted ldsm addresses: maddr(ks,tp) = base_tp[tp] + ks*2048
    unsigned base_tp[4];
    {
        unsigned row_base = swb_base + (unsigned)((((sub & 1) << 3) + lr) * 128);
        #pragma unroll
        for (int tp = 0; tp < 4; tp++)
            base_tp[tp] = row_base
                        + (unsigned)((((tp << 1) + (sub >> 1)) ^ lr) << 4);
    }

    // ---- MMA phase: hid = relu(VV @ W + b); score = hid . at_h ------------
    #pragma unroll 1
    for (int it = 0; it < 4; it++) {
        const int mbase = (w * 4 + it) << 4;          // 16 pairs per m-tile
        const int p0 = mbase + qr, p1 = p0 + 8;
        const unsigned pij0 = sPij[p0], pij1 = sPij[p1];
        const int eI0 = pij0 & 0xffffu, eJ0 = pij0 >> 16;
        const int eI1 = pij1 & 0xffffu, eJ1 = pij1 >> 16;

        // preload all A fragments for this m-tile (16 regs)
        unsigned fa[4][4];
        #pragma unroll
        for (int ks = 0; ks < 4; ks++) {
            const int k0 = (ks << 4) + qc2;
            fa[ks][0] = hmul2u(*(const unsigned*)&vb[eI0 + k0],
                               *(const unsigned*)&vb[eJ0 + k0]);
            fa[ks][1] = hmul2u(*(const unsigned*)&vb[eI1 + k0],
                               *(const unsigned*)&vb[eJ1 + k0]);
            fa[ks][2] = hmul2u(*(const unsigned*)&vb[eI0 + k0 + 8],
                               *(const unsigned*)&vb[eJ0 + k0 + 8]);
            fa[ks][3] = hmul2u(*(const unsigned*)&vb[eI1 + k0 + 8],
                               *(const unsigned*)&vb[eJ1 + k0 + 8]);
        }

        float s0 = 0.f, s1 = 0.f;
        #pragma unroll
        for (int tp = 0; tp < 4; tp++) {
            float acc2[2][4];
            #pragma unroll
            for (int u = 0; u < 2; u++)
                acc2[u][0] = acc2[u][1] = acc2[u][2] = acc2[u][3] = 0.f;

            #pragma unroll
            for (int ks = 0; ks < 4; ks++) {
                unsigned maddr = base_tp[tp] + (unsigned)(ks << 11);
                unsigned fb0, fb1, fb2, fb3;
                ldsm_x4_trans(fb0, fb1, fb2, fb3, maddr);
                mma_bf16_16x8x16(acc2[0], fa[ks][0], fa[ks][1], fa[ks][2], fa[ks][3], fb0, fb1);
                mma_bf16_16x8x16(acc2[1], fa[ks][0], fa[ks][1], fa[ks][2], fa[ks][3], fb2, fb3);
            }

            #pragma unroll
            for (int u = 0; u < 2; u++) {
                int h0 = (((tp << 1) + u) << 3) + qc2;
                float2 ab = *(const float2*)&sAb[h0];
                float2 ah = *(const float2*)&sAth[h0];
                s0 += fmaxf(acc2[u][0] + ab.x, 0.f) * ah.x
                    + fmaxf(acc2[u][1] + ab.y, 0.f) * ah.y;
                s1 += fmaxf(acc2[u][2] + ab.x, 0.f) * ah.x
                    + fmaxf(acc2[u][3] + ab.y, 0.f) * ah.y;
            }
        }

        s0 += __shfl_xor_sync(0xffffffffu, s0, 1);
        s0 += __shfl_xor_sync(0xffffffffu, s0, 2);
        s1 += __shfl_xor_sync(0xffffffffu, s1, 1);
        s1 += __shfl_xor_sync(0xffffffffu, s1, 2);
        if ((L & 3) == 0) {
            sScore[p0] = (p0 < NPAIR) ? s0 : 0.f;
            sScore[p1] = (p1 < NPAIR) ? s1 : 0.f;
        }
    }
    __syncthreads();

    // ---- pooling: pooled[k] = sum_p VV[p,k]*score[p]; lane owns k=2L,2L+1 --
    float pooled0 = 0.f, pooled1 = 0.f;
    const int base = w << 6;
    const int kb = L << 1;
    #pragma unroll 4
    for (int g4 = 0; g4 < 64; g4 += 4) {
        float4 sc  = *(const float4*)&sScore[base + g4];   // broadcast
        uint4  pj4 = *(const uint4*)&sPij[base + g4];      // broadcast
        unsigned pw[4] = {pj4.x, pj4.y, pj4.z, pj4.w};
        float sv[4] = {sc.x, sc.y, sc.z, sc.w};
        #pragma unroll
        for (int r = 0; r < 4; r++) {
            int eI = pw[r] & 0xffffu, eJ = pw[r] >> 16;
            unsigned prod = hmul2u(*(const unsigned*)&vb[eI + kb],
                                   *(const unsigned*)&vb[eJ + kb]);
            float2 pf = __bfloat1622float2(*(__nv_bfloat162*)&prod);
            pooled0 = fmaf(pf.x, sv[r], pooled0);
            pooled1 = fmaf(pf.y, sv[r], pooled1);
        }
    }
    atomicAdd(&sPooled[kb],     pooled0);
    atomicAdd(&sPooled[kb + 1], pooled1);
    __syncthreads();

    if (w == 0) {
        float d = sPooled[kb] * sP[kb] + sPooled[kb + 1] * sP[kb + 1];
        #pragma unroll
        for (int off = 16; off; off >>= 1) d += __shfl_xor_sync(0xffffffffu, d, off);
        if (L == 0) {
            float logit = d + sFm1;
            out[b] = 1.f / (1.f + expf(-logit));
        }
    }
}

extern "C" void kernel_launch(void* const* d_in, const int* in_sizes, int n_in,
                              void* d_out, int out_size) {
    (void)in_sizes; (void)n_in; (void)out_size;
    const int*   x    = (const int*)  d_in[0];
    const float* emb  = (const float*)d_in[1];
    const float* at_w = (const float*)d_in[2];
    const float* at_b = (const float*)d_in[3];
    const float* at_h = (const float*)d_in[4];
    const float* pvec = (const float*)d_in[5];
    const float* w0   = (const float*)d_in[6];
    const float* w1   = (const float*)d_in[7];
    float* out = (float*)d_out;

    afm_init<<<16, 256>>>(at_w);
    afm_kernel<<<BB, NTHREADS>>>(x, emb, at_b, at_h, pvec, w0, w1, out);
}